// round 8
// baseline (speedup 1.0000x reference)
#include <cuda_runtime.h>
#include <cuda_fp16.h>
#include <cstdint>

#define B   32
#define C   128
#define H   64
#define W   64
#define KM  4
#define O   256
#define RED 32
#define HW  4096
#define KDIM 1152

// ---------------- device scratch (module globals, no allocation) ------------
__device__ float g_pooled[B * C];          // SUM over pixels (scaled in attn)
__device__ float g_att[B * KM];
__device__ __align__(256) __half g_xt[(size_t)B * HW * C];      // xT [b][pix][c]
__device__ __align__(256) __half g_wk[(size_t)B * O * 9 * C];   // wk [b][o][tap][c]
__device__ __align__(256) __half g_zero[C];                     // 256B of zeros

// ---------------- PTX helpers (family-independent) -------------
__device__ __forceinline__ uint32_t smem_to_u32(const void* p) {
    uint32_t a;
    asm("{ .reg .u64 t; cvta.to.shared.u64 t, %1; cvt.u32.u64 %0, t; }" : "=r"(a) : "l"(p));
    return a;
}
__device__ __forceinline__ void cp_bulk(uint32_t dst, const void* src, uint32_t bytes, uint32_t mbar) {
    asm volatile("cp.async.bulk.shared::cta.global.mbarrier::complete_tx::bytes [%0], [%1], %2, [%3];"
        :: "r"(dst), "l"(src), "r"(bytes), "r"(mbar) : "memory");
}
#define MBARRIER_INIT(mbar, c) \
    asm volatile("mbarrier.init.shared.b64 [%0], %1;" :: "r"((uint32_t)(mbar)), "r"((uint32_t)(c)) : "memory")
#define MBARRIER_INVAL(mbar) \
    asm volatile("mbarrier.inval.shared.b64 [%0];" :: "r"((uint32_t)(mbar)) : "memory")
#define MBARRIER_ARRIVE_EXPECT_TX(mbar, bytes) \
    asm volatile("mbarrier.arrive.expect_tx.shared.b64 _, [%0], %1;" \
        :: "r"((uint32_t)(mbar)), "r"((uint32_t)(bytes)) : "memory")
#define FENCE_PROXY_ASYNC() asm volatile("fence.proxy.async.shared::cta;" ::: "memory")

#define MBARRIER_WAIT_PARITY(mbar_smem_addr, phase_parity) do { \
    uint32_t _mbar = (uint32_t)(mbar_smem_addr); \
    uint32_t _parity = (uint32_t)(phase_parity); \
    uint32_t _done; \
    asm volatile("{\n\t.reg .pred p;\n\t" \
        "mbarrier.try_wait.parity.acquire.cta.shared::cta.b64 p, [%1], %2;\n\t" \
        "selp.b32 %0, 1, 0, p;\n\t}" \
        : "=r"(_done) : "r"(_mbar), "r"(_parity) : "memory"); \
    if (!_done) { \
        asm volatile("{\n\t.reg .pred P1;\n\t" \
            "WAIT_LOOP_%=:\n\t" \
            "mbarrier.try_wait.parity.acquire.cta.shared::cta.b64 P1, [%0], %1, 0x989680;\n\t" \
            "@P1 bra.uni WAIT_DONE_%=;\n\t" \
            "bra.uni WAIT_LOOP_%=;\n\t" \
            "WAIT_DONE_%=:\n\t}" \
            :: "r"(_mbar), "r"(_parity) : "memory"); \
    } \
} while(0)

#define LDSM_X4(r, addr) \
    asm volatile("ldmatrix.sync.aligned.m8n8.x4.shared.b16 {%0,%1,%2,%3}, [%4];" \
        : "=r"((r)[0]), "=r"((r)[1]), "=r"((r)[2]), "=r"((r)[3]) : "r"(addr))

// f16 accumulator variant: d is 2x f16x2 registers
__device__ __forceinline__ void mma16816_h(uint32_t* d, const uint32_t* a, uint32_t b0, uint32_t b1) {
    asm volatile("mma.sync.aligned.m16n8k16.row.col.f16.f16.f16.f16 "
        "{%0,%1}, {%2,%3,%4,%5}, {%6,%7}, {%0,%1};"
        : "+r"(d[0]), "+r"(d[1])
        : "r"(a[0]), "r"(a[1]), "r"(a[2]), "r"(a[3]), "r"(b0), "r"(b1));
}

// ---------------------------------------------------------------------------
// 0) zero the pooled accumulator
// ---------------------------------------------------------------------------
__global__ void zero_kernel() {
    for (int i = threadIdx.x; i < B * C; i += 128) g_pooled[i] = 0.f;
}

// ---------------------------------------------------------------------------
// 1) x transpose -> xT[b][pix][c] fp16, FUSED with avg-pool partial sums.
// ---------------------------------------------------------------------------
__global__ void xt_kernel(const float* __restrict__ x) {
    int b = blockIdx.y;
    int p0 = blockIdx.x * 64;
    __shared__ float sm[64][C + 1];
    const float* xb = x + (size_t)b * C * HW + p0;
    for (int idx = threadIdx.x; idx < 64 * C; idx += 256) {
        int c = idx >> 6, p = idx & 63;
        sm[p][c] = xb[(size_t)c * HW + p];
    }
    __syncthreads();
    __half* oh = g_xt + ((size_t)b * HW + p0) * C;
    for (int idx = threadIdx.x; idx < 64 * C; idx += 256) {
        int p = idx >> 7, c = idx & 127;
        oh[(size_t)p * C + c] = __float2half_rn(sm[p][c]);
    }
    if (threadIdx.x < C) {
        int c = threadIdx.x;
        float s = 0.f;
        #pragma unroll 8
        for (int p = 0; p < 64; p++) s += sm[p][c];
        atomicAdd(&g_pooled[b * C + c], s);
    }
}

// ---------------------------------------------------------------------------
// 2) Attention MLP + softmax (one thread per batch).  pooled holds SUMS.
// ---------------------------------------------------------------------------
__global__ void attn_kernel(const float* __restrict__ w1, const float* __restrict__ b1,
                            const float* __restrict__ w2, const float* __restrict__ b2) {
    int b = threadIdx.x;
    if (b >= B) return;
    const float inv_hw = 1.f / (float)HW;
    const float* pb = g_pooled + b * C;
    float h[RED];
    #pragma unroll 4
    for (int r = 0; r < RED; r++) {
        float s = 0.f;
        const float* wr = w1 + r * C;
        #pragma unroll 8
        for (int c = 0; c < C; c++) s += pb[c] * wr[c];
        h[r] = fmaxf(s * inv_hw + b1[r], 0.f);
    }
    float logits[KM];
    float mx = -1e30f;
    #pragma unroll
    for (int k = 0; k < KM; k++) {
        float s = b2[k];
        const float* wr = w2 + k * RED;
        #pragma unroll
        for (int r = 0; r < RED; r++) s += h[r] * wr[r];
        logits[k] = s; mx = fmaxf(mx, s);
    }
    float den = 0.f;
    #pragma unroll
    for (int k = 0; k < KM; k++) { logits[k] = __expf(logits[k] - mx); den += logits[k]; }
    float inv = 1.f / den;
    #pragma unroll
    for (int k = 0; k < KM; k++) g_att[b * KM + k] = logits[k] * inv;
}

// ---------------------------------------------------------------------------
// 3) wk mix -> [b][o][tap][c] fp16.  One block per (o, b), 128 threads.
// ---------------------------------------------------------------------------
__global__ void wk_kernel(const float* __restrict__ weights) {
    int o = blockIdx.x, b = blockIdx.y;
    float a0 = g_att[b * KM + 0], a1 = g_att[b * KM + 1];
    float a2 = g_att[b * KM + 2], a3 = g_att[b * KM + 3];
    __shared__ __half sh[9 * C];
    const size_t ks = (size_t)O * KDIM;
    const float* wp = weights + (size_t)o * KDIM;
    for (int i = threadIdx.x; i < KDIM; i += 128) {
        float v = a0 * wp[i] + a1 * wp[ks + i] + a2 * wp[2 * ks + i] + a3 * wp[3 * ks + i];
        int c = i / 9, tap = i - c * 9;
        sh[tap * C + c] = __float2half_rn(v);
    }
    __syncthreads();
    size_t ob = ((size_t)b * O + o) * KDIM;
    uint4* dh = (uint4*)(g_wk + ob);
    const uint4* shv = (const uint4*)sh;
    for (int i = threadIdx.x; i < (KDIM * 2) / 16; i += 128) dh[i] = shv[i];
}

// ---------------------------------------------------------------------------
// 4) Conv GEMM via mma.sync fp16, f16 accumulators promoted to fp32 per tap.
//    CTA: M=128 x N=256, 512 threads (16 warps), warp tile 32x64.
//    9 stages (one tap, K=128), cp.async.bulk rows, double buffer.
// ---------------------------------------------------------------------------
#define RPADB   272
#define A_ROWS  128
#define B_ROWS  256
#define AT_BYTES (A_ROWS * RPADB)
#define BT_BYTES (B_ROWS * RPADB)
#define OFF_A   0
#define OFF_B   (AT_BYTES)
#define STAGE_BYTES (AT_BYTES + BT_BYTES)
#define NSTAGE  9
#define STAGE_TX (384u * 256u)
#define CONV_SMEM (1024 + 2 * STAGE_BYTES)

__global__ void __launch_bounds__(512, 1) conv_kernel(float* __restrict__ out) {
    extern __shared__ char smem[];
    uint32_t sb = smem_to_u32(smem);
    uint32_t mbar0 = sb;
    uint32_t tiles = sb + 1024;
    int tid = threadIdx.x;
    int lane = tid & 31, wid = tid >> 5;
    int b  = blockIdx.z;
    int m0 = blockIdx.y * 128;
    int n0 = blockIdx.x * 256;
    int wm = (wid & 3) * 32;
    int wn = (wid >> 2) * 64;

    if (tid == 0) { MBARRIER_INIT(mbar0, 1); MBARRIER_INIT(mbar0 + 8, 1); }
    __syncthreads();

    const __half* wk = g_wk + ((size_t)b * O + m0) * KDIM;
    const __half* xt = g_xt + (size_t)b * HW * C;

    auto load_stage = [&](int s) {
        uint32_t mbar = mbar0 + (uint32_t)(s & 1) * 8;
        uint32_t base = tiles + (uint32_t)(s & 1) * STAGE_BYTES;
        FENCE_PROXY_ASYNC();
        if (tid == 0) MBARRIER_ARRIVE_EXPECT_TX(mbar, STAGE_TX);
        __syncthreads();
        int tap = s;
        int dy = tap / 3 - 1, dx = tap % 3 - 1;
        if (tid < 128) {
            cp_bulk(base + OFF_A + (uint32_t)tid * RPADB,
                    wk + (size_t)tid * KDIM + (size_t)tap * C, 256, mbar);
        } else if (tid < 384) {
            int row = tid - 128;
            int p = n0 + row;
            int iy = (p >> 6) + dy, ix = (p & 63) + dx;
            bool valid = ((unsigned)iy < 64u) && ((unsigned)ix < 64u);
            const __half* src = valid ? (xt + (size_t)(p + dy * 64 + dx) * C) : g_zero;
            cp_bulk(base + OFF_B + (uint32_t)row * RPADB, src, 256, mbar);
        }
    };

    float acc[2][8][4];
    #pragma unroll
    for (int i = 0; i < 2; i++)
        #pragma unroll
        for (int j = 0; j < 8; j++)
            #pragma unroll
            for (int q = 0; q < 4; q++) acc[i][j][q] = 0.f;

    load_stage(0);
    load_stage(1);

    uint32_t a_row = (uint32_t)(wm + (lane & 15));
    uint32_t a_kb  = (uint32_t)((lane >> 4) * 16);
    uint32_t b_row = (uint32_t)(wn + (lane & 7) + ((lane >> 4) & 1) * 8);
    uint32_t b_kb  = (uint32_t)(((lane >> 3) & 1) * 16);

    #pragma unroll 1
    for (int s = 0; s < NSTAGE; s++) {
        MBARRIER_WAIT_PARITY(mbar0 + (uint32_t)(s & 1) * 8, (s >> 1) & 1);

        uint32_t base = tiles + (uint32_t)(s & 1) * STAGE_BYTES;

        // per-tap f16 accumulators (zeroed each stage)
        uint32_t acch[2][8][2];
        #pragma unroll
        for (int i = 0; i < 2; i++)
            #pragma unroll
            for (int j = 0; j < 8; j++) { acch[i][j][0] = 0u; acch[i][j][1] = 0u; }

        #pragma unroll
        for (int kk = 0; kk < 8; kk++) {
            uint32_t kb = (uint32_t)(kk * 32);
            uint32_t ah[2][4];
            #pragma unroll
            for (int mt = 0; mt < 2; mt++) {
                uint32_t off = (a_row + mt * 16) * RPADB + kb + a_kb;
                LDSM_X4(ah[mt], base + OFF_A + off);
            }
            #pragma unroll
            for (int g = 0; g < 4; g++) {
                uint32_t off = (b_row + g * 16) * RPADB + kb + b_kb;
                uint32_t bh[4];
                LDSM_X4(bh, base + OFF_B + off);
                #pragma unroll
                for (int mt = 0; mt < 2; mt++) {
                    #pragma unroll
                    for (int nt = 0; nt < 2; nt++) {
                        mma16816_h(acch[mt][g * 2 + nt], ah[mt], bh[nt * 2], bh[nt * 2 + 1]);
                    }
                }
            }
        }

        // promote tap partials to fp32
        #pragma unroll
        for (int mt = 0; mt < 2; mt++) {
            #pragma unroll
            for (int j = 0; j < 8; j++) {
                float2 lo = __half22float2(*(__half2*)&acch[mt][j][0]);
                float2 hi = __half22float2(*(__half2*)&acch[mt][j][1]);
                acc[mt][j][0] += lo.x;
                acc[mt][j][1] += lo.y;
                acc[mt][j][2] += hi.x;
                acc[mt][j][3] += hi.y;
            }
        }

        __syncthreads();
        if (s + 2 < NSTAGE) load_stage(s + 2);
    }

    // epilogue: warp writes 32x64 block
    float* ob = out + ((size_t)b * O + m0) * HW + n0;
    #pragma unroll
    for (int mt = 0; mt < 2; mt++) {
        int r = wm + mt * 16 + (lane >> 2);
        #pragma unroll
        for (int nti = 0; nti < 8; nti++) {
            int cn = wn + nti * 8 + 2 * (lane & 3);
            float2 v0 = make_float2(acc[mt][nti][0], acc[mt][nti][1]);
            float2 v1 = make_float2(acc[mt][nti][2], acc[mt][nti][3]);
            *(float2*)(ob + (size_t)r * HW + cn) = v0;
            *(float2*)(ob + (size_t)(r + 8) * HW + cn) = v1;
        }
    }
    __syncthreads();
    if (tid == 0) { MBARRIER_INVAL(mbar0); MBARRIER_INVAL(mbar0 + 8); }
}

// ---------------------------------------------------------------------------
extern "C" void kernel_launch(void* const* d_in, const int* in_sizes, int n_in,
                              void* d_out, int out_size) {
    const float* x       = (const float*)d_in[0];
    const float* weights = (const float*)d_in[1];
    const float* w1      = (const float*)d_in[2];
    const float* b1      = (const float*)d_in[3];
    const float* w2      = (const float*)d_in[4];
    const float* b2      = (const float*)d_in[5];
    float* out = (float*)d_out;

    zero_kernel<<<1, 128>>>();
    xt_kernel<<<dim3(HW / 64, B), 256>>>(x);
    attn_kernel<<<1, 32>>>(w1, b1, w2, b2);
    wk_kernel<<<dim3(O, B), 128>>>(weights);

    cudaFuncSetAttribute(conv_kernel, cudaFuncAttributeMaxDynamicSharedMemorySize, CONV_SMEM);
    conv_kernel<<<dim3(HW / 256, O / 128, B), 512, CONV_SMEM>>>(out);
}

// round 9
// speedup vs baseline: 1.5479x; 1.5479x over previous
#include <cuda_runtime.h>
#include <cuda_fp16.h>
#include <cstdint>

#define B   32
#define C   128
#define H   64
#define W   64
#define KM  4
#define O   256
#define RED 32
#define HW  4096
#define KDIM 1152

// ---------------- device scratch (module globals, no allocation) ------------
__device__ float g_pooled[B * C];          // SUM over pixels (scaled in attn)
__device__ float g_att[B * KM];
__device__ __align__(256) __half g_xt[(size_t)B * HW * C];      // xT [b][pix][c]
__device__ __align__(256) __half g_wk[(size_t)B * O * 9 * C];   // wk [b][o][tap][c]
__device__ __align__(256) __half g_zero[C];                     // 256B of zeros

// ---------------- PTX helpers (family-independent) -------------
__device__ __forceinline__ uint32_t smem_to_u32(const void* p) {
    uint32_t a;
    asm("{ .reg .u64 t; cvta.to.shared.u64 t, %1; cvt.u32.u64 %0, t; }" : "=r"(a) : "l"(p));
    return a;
}
__device__ __forceinline__ void cp_bulk(uint32_t dst, const void* src, uint32_t bytes, uint32_t mbar) {
    asm volatile("cp.async.bulk.shared::cta.global.mbarrier::complete_tx::bytes [%0], [%1], %2, [%3];"
        :: "r"(dst), "l"(src), "r"(bytes), "r"(mbar) : "memory");
}
#define MBARRIER_INIT(mbar, c) \
    asm volatile("mbarrier.init.shared.b64 [%0], %1;" :: "r"((uint32_t)(mbar)), "r"((uint32_t)(c)) : "memory")
#define MBARRIER_INVAL(mbar) \
    asm volatile("mbarrier.inval.shared.b64 [%0];" :: "r"((uint32_t)(mbar)) : "memory")
#define MBARRIER_ARRIVE_EXPECT_TX(mbar, bytes) \
    asm volatile("mbarrier.arrive.expect_tx.shared.b64 _, [%0], %1;" \
        :: "r"((uint32_t)(mbar)), "r"((uint32_t)(bytes)) : "memory")
#define FENCE_PROXY_ASYNC() asm volatile("fence.proxy.async.shared::cta;" ::: "memory")

#define MBARRIER_WAIT_PARITY(mbar_smem_addr, phase_parity) do { \
    uint32_t _mbar = (uint32_t)(mbar_smem_addr); \
    uint32_t _parity = (uint32_t)(phase_parity); \
    uint32_t _done; \
    asm volatile("{\n\t.reg .pred p;\n\t" \
        "mbarrier.try_wait.parity.acquire.cta.shared::cta.b64 p, [%1], %2;\n\t" \
        "selp.b32 %0, 1, 0, p;\n\t}" \
        : "=r"(_done) : "r"(_mbar), "r"(_parity) : "memory"); \
    if (!_done) { \
        asm volatile("{\n\t.reg .pred P1;\n\t" \
            "WAIT_LOOP_%=:\n\t" \
            "mbarrier.try_wait.parity.acquire.cta.shared::cta.b64 P1, [%0], %1, 0x989680;\n\t" \
            "@P1 bra.uni WAIT_DONE_%=;\n\t" \
            "bra.uni WAIT_LOOP_%=;\n\t" \
            "WAIT_DONE_%=:\n\t}" \
            :: "r"(_mbar), "r"(_parity) : "memory"); \
    } \
} while(0)

#define LDSM_X4(r, addr) \
    asm volatile("ldmatrix.sync.aligned.m8n8.x4.shared.b16 {%0,%1,%2,%3}, [%4];" \
        : "=r"((r)[0]), "=r"((r)[1]), "=r"((r)[2]), "=r"((r)[3]) : "r"(addr))

__device__ __forceinline__ void mma16816(float* d, const uint32_t* a, uint32_t b0, uint32_t b1) {
    asm volatile("mma.sync.aligned.m16n8k16.row.col.f32.f16.f16.f32 "
        "{%0,%1,%2,%3}, {%4,%5,%6,%7}, {%8,%9}, {%0,%1,%2,%3};"
        : "+f"(d[0]), "+f"(d[1]), "+f"(d[2]), "+f"(d[3])
        : "r"(a[0]), "r"(a[1]), "r"(a[2]), "r"(a[3]), "r"(b0), "r"(b1));
}

// ---------------------------------------------------------------------------
// 0) zero the pooled accumulator
// ---------------------------------------------------------------------------
__global__ void zero_kernel() {
    for (int i = threadIdx.x; i < B * C; i += 128) g_pooled[i] = 0.f;
}

// ---------------------------------------------------------------------------
// 1) x transpose -> xT[b][pix][c] fp16, FUSED with avg-pool partial sums.
// ---------------------------------------------------------------------------
__global__ void xt_kernel(const float* __restrict__ x) {
    int b = blockIdx.y;
    int p0 = blockIdx.x * 64;
    __shared__ float sm[64][C + 1];
    const float* xb = x + (size_t)b * C * HW + p0;
    for (int idx = threadIdx.x; idx < 64 * C; idx += 256) {
        int c = idx >> 6, p = idx & 63;
        sm[p][c] = xb[(size_t)c * HW + p];
    }
    __syncthreads();
    __half* oh = g_xt + ((size_t)b * HW + p0) * C;
    for (int idx = threadIdx.x; idx < 64 * C; idx += 256) {
        int p = idx >> 7, c = idx & 127;
        oh[(size_t)p * C + c] = __float2half_rn(sm[p][c]);
    }
    if (threadIdx.x < C) {
        int c = threadIdx.x;
        float s = 0.f;
        #pragma unroll 8
        for (int p = 0; p < 64; p++) s += sm[p][c];
        atomicAdd(&g_pooled[b * C + c], s);
    }
}

// ---------------------------------------------------------------------------
// 2) Attention MLP + softmax (one thread per batch).  pooled holds SUMS.
// ---------------------------------------------------------------------------
__global__ void attn_kernel(const float* __restrict__ w1, const float* __restrict__ b1,
                            const float* __restrict__ w2, const float* __restrict__ b2) {
    int b = threadIdx.x;
    if (b >= B) return;
    const float inv_hw = 1.f / (float)HW;
    const float* pb = g_pooled + b * C;
    float h[RED];
    #pragma unroll 4
    for (int r = 0; r < RED; r++) {
        float s = 0.f;
        const float* wr = w1 + r * C;
        #pragma unroll 8
        for (int c = 0; c < C; c++) s += pb[c] * wr[c];
        h[r] = fmaxf(s * inv_hw + b1[r], 0.f);
    }
    float logits[KM];
    float mx = -1e30f;
    #pragma unroll
    for (int k = 0; k < KM; k++) {
        float s = b2[k];
        const float* wr = w2 + k * RED;
        #pragma unroll
        for (int r = 0; r < RED; r++) s += h[r] * wr[r];
        logits[k] = s; mx = fmaxf(mx, s);
    }
    float den = 0.f;
    #pragma unroll
    for (int k = 0; k < KM; k++) { logits[k] = __expf(logits[k] - mx); den += logits[k]; }
    float inv = 1.f / den;
    #pragma unroll
    for (int k = 0; k < KM; k++) g_att[b * KM + k] = logits[k] * inv;
}

// ---------------------------------------------------------------------------
// 3) wk mix -> [b][o][tap][c] fp16.  One block per (o, b), 128 threads.
// ---------------------------------------------------------------------------
__global__ void wk_kernel(const float* __restrict__ weights) {
    int o = blockIdx.x, b = blockIdx.y;
    float a0 = g_att[b * KM + 0], a1 = g_att[b * KM + 1];
    float a2 = g_att[b * KM + 2], a3 = g_att[b * KM + 3];
    __shared__ __half sh[9 * C];
    const size_t ks = (size_t)O * KDIM;
    const float* wp = weights + (size_t)o * KDIM;
    for (int i = threadIdx.x; i < KDIM; i += 128) {
        float v = a0 * wp[i] + a1 * wp[ks + i] + a2 * wp[2 * ks + i] + a3 * wp[3 * ks + i];
        int c = i / 9, tap = i - c * 9;
        sh[tap * C + c] = __float2half_rn(v);
    }
    __syncthreads();
    size_t ob = ((size_t)b * O + o) * KDIM;
    uint4* dh = (uint4*)(g_wk + ob);
    const uint4* shv = (const uint4*)sh;
    for (int i = threadIdx.x; i < (KDIM * 2) / 16; i += 128) dh[i] = shv[i];
}

// ---------------------------------------------------------------------------
// 4) Conv GEMM via mma.sync fp16 (fp32 acc).
//    CTA: M=128 x N=128, 256 threads (8 warps), warp tile 32x64 (4M x 2N).
//    Single-stage buffer, 2 CTAs/SM co-residency does the double buffering.
//    9 stages (one tap each, K=128), cp.async.bulk 256B rows.
// ---------------------------------------------------------------------------
#define RPADB   272
#define A_ROWS  128
#define B_ROWS  128
#define AT_BYTES (A_ROWS * RPADB)         // 34816
#define BT_BYTES (B_ROWS * RPADB)         // 34816
#define OFF_A   0
#define OFF_B   (AT_BYTES)
#define STAGE_BYTES (AT_BYTES + BT_BYTES) // 69632
#define NSTAGE  9
#define STAGE_TX (256u * 256u)            // 65536 bytes per stage
#define CONV_SMEM (1024 + STAGE_BYTES)    // 70656

__global__ void __launch_bounds__(256, 2) conv_kernel(float* __restrict__ out) {
    extern __shared__ char smem[];
    uint32_t sb = smem_to_u32(smem);
    uint32_t mbar = sb;
    uint32_t tiles = sb + 1024;
    int tid = threadIdx.x;
    int lane = tid & 31, wid = tid >> 5;
    int b  = blockIdx.z;
    int m0 = blockIdx.y * 128;
    int n0 = blockIdx.x * 128;
    int wm = (wid & 3) * 32;       // warp M offset (4 M-groups)
    int wn = (wid >> 2) * 64;      // warp N offset (2 N-groups)

    if (tid == 0) MBARRIER_INIT(mbar, 1);
    __syncthreads();

    const __half* wk = g_wk + ((size_t)b * O + m0) * KDIM;
    const __half* xt = g_xt + (size_t)b * HW * C;

    auto load_stage = [&](int s) {
        // caller guarantees all reads of the buffer are done (syncthreads)
        FENCE_PROXY_ASYNC();
        if (tid == 0) MBARRIER_ARRIVE_EXPECT_TX(mbar, STAGE_TX);
        __syncthreads();
        int tap = s;
        int dy = tap / 3 - 1, dx = tap % 3 - 1;
        if (tid < 128) {
            cp_bulk(tiles + OFF_A + (uint32_t)tid * RPADB,
                    wk + (size_t)tid * KDIM + (size_t)tap * C, 256, mbar);
        } else {
            int row = tid - 128;
            int p = n0 + row;
            int iy = (p >> 6) + dy, ix = (p & 63) + dx;
            bool valid = ((unsigned)iy < 64u) && ((unsigned)ix < 64u);
            const __half* src = valid ? (xt + (size_t)(p + dy * 64 + dx) * C) : g_zero;
            cp_bulk(tiles + OFF_B + (uint32_t)row * RPADB, src, 256, mbar);
        }
    };

    float acc[2][8][4];
    #pragma unroll
    for (int i = 0; i < 2; i++)
        #pragma unroll
        for (int j = 0; j < 8; j++)
            #pragma unroll
            for (int q = 0; q < 4; q++) acc[i][j][q] = 0.f;

    load_stage(0);

    // ldmatrix lane geometry (non-trans; k-contiguous rows)
    uint32_t a_row = (uint32_t)(wm + (lane & 15));
    uint32_t a_kb  = (uint32_t)((lane >> 4) * 16);
    uint32_t b_row = (uint32_t)(wn + (lane & 7) + ((lane >> 4) & 1) * 8);
    uint32_t b_kb  = (uint32_t)(((lane >> 3) & 1) * 16);

    #pragma unroll 1
    for (int s = 0; s < NSTAGE; s++) {
        MBARRIER_WAIT_PARITY(mbar, s & 1);

        #pragma unroll
        for (int kk = 0; kk < 8; kk++) {
            uint32_t kb = (uint32_t)(kk * 32);      // k16 step = 32B
            uint32_t ah[2][4];
            #pragma unroll
            for (int mt = 0; mt < 2; mt++) {
                uint32_t off = (a_row + mt * 16) * RPADB + kb + a_kb;
                LDSM_X4(ah[mt], tiles + OFF_A + off);
            }
            #pragma unroll
            for (int g = 0; g < 4; g++) {
                uint32_t off = (b_row + g * 16) * RPADB + kb + b_kb;
                uint32_t bh[4];
                LDSM_X4(bh, tiles + OFF_B + off);
                #pragma unroll
                for (int mt = 0; mt < 2; mt++) {
                    #pragma unroll
                    for (int nt = 0; nt < 2; nt++) {
                        mma16816(acc[mt][g * 2 + nt], ah[mt], bh[nt * 2], bh[nt * 2 + 1]);
                    }
                }
            }
        }
        __syncthreads();                 // all reads of the single buffer done
        if (s + 1 < NSTAGE) load_stage(s + 1);
    }

    // epilogue: warp writes 32x64 block
    float* ob = out + ((size_t)b * O + m0) * HW + n0;
    #pragma unroll
    for (int mt = 0; mt < 2; mt++) {
        int r = wm + mt * 16 + (lane >> 2);
        #pragma unroll
        for (int nti = 0; nti < 8; nti++) {
            int cn = wn + nti * 8 + 2 * (lane & 3);
            float2 v0 = make_float2(acc[mt][nti][0], acc[mt][nti][1]);
            float2 v1 = make_float2(acc[mt][nti][2], acc[mt][nti][3]);
            *(float2*)(ob + (size_t)r * HW + cn) = v0;
            *(float2*)(ob + (size_t)(r + 8) * HW + cn) = v1;
        }
    }
    __syncthreads();
    if (tid == 0) MBARRIER_INVAL(mbar);
}

// ---------------------------------------------------------------------------
extern "C" void kernel_launch(void* const* d_in, const int* in_sizes, int n_in,
                              void* d_out, int out_size) {
    const float* x       = (const float*)d_in[0];
    const float* weights = (const float*)d_in[1];
    const float* w1      = (const float*)d_in[2];
    const float* b1      = (const float*)d_in[3];
    const float* w2      = (const float*)d_in[4];
    const float* b2      = (const float*)d_in[5];
    float* out = (float*)d_out;

    zero_kernel<<<1, 128>>>();
    xt_kernel<<<dim3(HW / 64, B), 256>>>(x);
    attn_kernel<<<1, 32>>>(w1, b1, w2, b2);
    wk_kernel<<<dim3(O, B), 128>>>(weights);

    cudaFuncSetAttribute(conv_kernel, cudaFuncAttributeMaxDynamicSharedMemorySize, CONV_SMEM);
    conv_kernel<<<dim3(HW / 128, O / 128, B), 256, CONV_SMEM>>>(out);
}